// round 15
// baseline (speedup 1.0000x reference)
#include <cuda_runtime.h>
#include <cuda_bf16.h>
#include <math.h>

// Problem constants
#define NN 8192
#define KK 64
#define NB 1024
#define XLO (-6.0f)
#define BW_INVF (1024.0f / 12.0f)   // 1/bucket_width = 85.3333
#define RWIN 9                      // excluded pairs: |d| > 9*w = 0.10547 > 0.10335 support -> exp == 0.0f
#define WBINS (2 * RWIN + 1)        // 19 bins per group window
#define GRID 256
#define TPB 512
#define NGRP 4                      // own buckets per block (stride 256 in bucket space)
#define NBIN (NGRP * WBINS)         // 76 local bins
#define GSLABC 64                   // global per-bucket slab capacity (peak bucket ~38)
#define SCAP 2048                   // per-block staged capacity (worst ~800)
#define PSPLIT 16                   // threads per own element in KDE

// -8192 * log2(e): EX2 argument scale
#define C2L (-11818.558f)

// Persistent global state
__device__ int   g_bar;                    // monotonic barrier counter
__device__ int   g_cnt;                    // monotonic last-block counter
__device__ int   g_bcnt[NB];               // per-bucket counts (zeroed by last block each call)
__device__ float g_slab[NB][GSLABC];       // per-bucket value slabs (atomic order)
__device__ float g_part[GRID];

__device__ __forceinline__ float ex2f(float y) {
    float r;
    asm("ex2.approx.f32 %0, %1;" : "=f"(r) : "f"(y));
    return r;
}

// Software global barrier: monotonic counter, graph-replay safe.
__device__ __forceinline__ void gbar() {
    __syncthreads();
    if (threadIdx.x == 0) {
        __threadfence();
        int tok = atomicAdd(&g_bar, 1);
        int target = (tok & ~(GRID - 1)) + GRID;
        while (*((volatile int*)&g_bar) < target) { }
        __threadfence();
    }
    __syncthreads();
}

__global__ void __launch_bounds__(TPB, 3)
gmm_fused(const float* __restrict__ x,
          const float* __restrict__ weight_logits,
          const float* __restrict__ means,
          const float* __restrict__ log_vars,
          float* __restrict__ out)
{
    __shared__ float raw[SCAP];             // window values (slab order)
    __shared__ float srt[SCAP];             // window values (canonical sorted)
    __shared__ int   bcs[NBIN];             // local bin counts
    __shared__ int   boff[NBIN + 1];
    __shared__ int   ownoff[NGRP + 1];
    __shared__ float sa[KK], sc[KK], smu[KK];
    __shared__ float red[TPB / 32];
    __shared__ float fred[GRID];
    __shared__ int   slast;

    const int tid  = threadIdx.x;
    const int blk  = blockIdx.x;
    const int lane = tid & 31;
    const int w    = tid >> 5;
    const unsigned FULL = 0xffffffffu;

    // ---- P1: classify THIS block's 32 elements into global slabs --------
    if (tid < 32) {
        float v = x[blk * 32 + tid];
        int b = __float2int_rd(fmaf(v, BW_INVF, 512.0f));   // (v - XLO) * BW_INVF
        b = min(max(b, 0), NB - 1);
        int p = atomicAdd(&g_bcnt[b], 1);
        if (p < GSLABC) g_slab[b][p] = v;
    }

    // ---- GMM constants (warp 1, concurrent with P1) ----------------------
    if (w == 1) {
        const float TWO_PI = 6.283185307179586f;
        float l0 = weight_logits[lane], l1 = weight_logits[lane + 32];
        float m = fmaxf(l0, l1);
        #pragma unroll
        for (int o = 16; o > 0; o >>= 1) m = fmaxf(m, __shfl_xor_sync(FULL, m, o));
        float e0 = expf(l0 - m), e1 = expf(l1 - m);
        float s = e0 + e1;
        #pragma unroll
        for (int o = 16; o > 0; o >>= 1) s += __shfl_xor_sync(FULL, s, o);
        float invs = 1.0f / s;

        float var0 = expf(log_vars[lane]);
        sa[lane]  = e0 * invs * rsqrtf(TWO_PI * var0);
        sc[lane]  = -0.5f / var0;
        smu[lane] = means[lane];
        float var1 = expf(log_vars[lane + 32]);
        sa[lane + 32]  = e1 * invs * rsqrtf(TWO_PI * var1);
        sc[lane + 32]  = -0.5f / var1;
        smu[lane + 32] = means[lane + 32];
    }

    gbar();   // the ONLY global barrier: slabs + counts published

    // ---- P2a: fetch the 76 window-bucket counts --------------------------
    // local bin l -> bucket B = blk + g*256 + (r - RWIN), g = l/19, r = l%19
    if (tid < NBIN) {
        int g = tid / WBINS, r = tid - g * WBINS;
        int B = blk + g * 256 + (r - RWIN);
        int c = 0;
        if (B >= 0 && B < NB) c = min(__ldcg(&g_bcnt[B]), GSLABC);
        bcs[tid] = c;
    }
    __syncthreads();

    // ---- P2b: prefix over 76 bins (warp 0) + own prefix (warp 1) ---------
    if (w == 0) {
        int base = lane * 3;
        int c[3]; int tot = 0;
        #pragma unroll
        for (int i = 0; i < 3; ++i) {
            int idx = base + i;
            c[i] = (idx < NBIN) ? bcs[idx] : 0;
            tot += c[i];
        }
        int incl = tot;
        #pragma unroll
        for (int o = 1; o < 32; o <<= 1) {
            int n = __shfl_up_sync(FULL, incl, o);
            if (lane >= o) incl += n;
        }
        int run = incl - tot;
        #pragma unroll
        for (int i = 0; i < 3; ++i) {
            int idx = base + i;
            if (idx < NBIN) boff[idx] = run;
            run += c[i];
        }
        if (lane == 31) boff[NBIN] = incl;
    }
    if (w == 1 && lane < NGRP) {
        int oc = bcs[lane * WBINS + RWIN];
        int incl = oc;
        #pragma unroll
        for (int o = 1; o < NGRP; o <<= 1) {
            int n = __shfl_up_sync(0xfu, incl, o, NGRP);
            if (lane >= o) incl += n;
        }
        ownoff[lane] = incl - oc;
        if (lane == NGRP - 1) ownoff[NGRP] = incl;
    }
    __syncthreads();

    // ---- P2c: warp-per-bin copy from global slab + canonical rank sort ----
    for (int l = w; l < NBIN; l += TPB / 32) {
        int g = l / WBINS, r = l - g * WBINS;
        int B = blk + g * 256 + (r - RWIN);
        int cnt = bcs[l];
        int lo  = boff[l];
        for (int pos = lane; pos < cnt; pos += 32)
            raw[lo + pos] = __ldcg(&g_slab[B][pos]);
        __syncwarp();
        for (int pos = lane; pos < cnt; pos += 32) {
            float val = raw[lo + pos];
            int rank = 0;
            int u = 0;
            for (; u + 4 <= cnt; u += 4) {
                float o0 = raw[lo + u + 0], o1 = raw[lo + u + 1];
                float o2 = raw[lo + u + 2], o3 = raw[lo + u + 3];
                rank += ((o0 < val) || (o0 == val && (u + 0) < pos))
                      + ((o1 < val) || (o1 == val && (u + 1) < pos))
                      + ((o2 < val) || (o2 == val && (u + 2) < pos))
                      + ((o3 < val) || (o3 == val && (u + 3) < pos));
            }
            for (; u < cnt; ++u) {
                float o = raw[lo + u];
                rank += (o < val) || (o == val && u < pos);
            }
            srt[lo + rank] = val;
        }
        __syncwarp();
    }
    __syncthreads();

    // ---- P3: KDE + mixture. 16 threads per own element -------------------
    const float invZ = (float)(1.0 / (0.0078125 * 2.5066282746310002 * 8192.0));
    const int M    = ownoff[NGRP];
    const int ESL  = TPB / PSPLIT;               // 32 element-slots per pass
    const int Mup  = (M + ESL - 1) / ESL * ESL;
    const int e0   = tid >> 4;
    const int p    = tid & (PSPLIT - 1);

    float acc = 0.0f;
    for (int e = e0; e < Mup; e += ESL) {
        bool active = (e < M);
        int g = 0;
        if (active)
            g = (e >= ownoff[1]) + (e >= ownoff[2]) + (e >= ownoff[3]);

        float xi = 0.0f;
        int a = 0, b = 0;
        if (active) {
            int pos = e - ownoff[g];
            xi = srt[boff[g * WBINS + RWIN] + pos];
            int wlo = boff[g * WBINS];
            int len = boff[g * WBINS + WBINS] - wlo;
            a = wlo + (p * len) / PSPLIT;
            b = wlo + ((p + 1) * len) / PSPLIT;
        }

        float s0 = 0.f, s1 = 0.f, s2 = 0.f, s3 = 0.f;
        int k = a;
        for (; k + 4 <= b; k += 4) {
            float u0 = srt[k + 0], u1 = srt[k + 1];
            float u2 = srt[k + 2], u3 = srt[k + 3];
            float d0 = xi - u0, d1 = xi - u1, d2 = xi - u2, d3 = xi - u3;
            s0 += ex2f(C2L * d0 * d0);
            s1 += ex2f(C2L * d1 * d1);
            s2 += ex2f(C2L * d2 * d2);
            s3 += ex2f(C2L * d3 * d3);
        }
        for (; k < b; ++k) {
            float d = xi - srt[k];
            s0 += ex2f(C2L * d * d);
        }
        float kde = (s0 + s1) + (s2 + s3);

        float m = 0.0f;
        #pragma unroll
        for (int c = p * 4; c < p * 4 + 4; ++c) {
            float d = xi - smu[c];
            m += sa[c] * __expf(sc[c] * d * d);
        }

        float part = active ? (m - invZ * kde) : 0.0f;
        part += __shfl_xor_sync(FULL, part, 8, 16);
        part += __shfl_xor_sync(FULL, part, 4, 16);
        part += __shfl_xor_sync(FULL, part, 2, 16);
        part += __shfl_xor_sync(FULL, part, 1, 16);
        if (p == 0 && active) acc += part * part;
    }

    // ---- block reduction (fixed order) -----------------------------------
    #pragma unroll
    for (int o = 16; o > 0; o >>= 1) acc += __shfl_xor_sync(FULL, acc, o);
    if (lane == 0) red[w] = acc;
    __syncthreads();
    if (w == 0) {
        float bsum = (lane < TPB / 32) ? red[lane] : 0.0f;
        #pragma unroll
        for (int o = 16; o > 0; o >>= 1) bsum += __shfl_xor_sync(FULL, bsum, o);
        if (lane == 0) {
            g_part[blk] = bsum;
            __threadfence();
            int old = atomicAdd(&g_cnt, 1);
            slast = (((old + 1) & (GRID - 1)) == 0);
        }
    }
    __syncthreads();

    // ---- last block: zero g_bcnt for next replay + fixed-order final sum --
    if (slast) {
        // all blocks have passed P2 (they published partials) -> safe to reset
        g_bcnt[tid] = 0;
        g_bcnt[tid + TPB] = 0;
        if (tid < GRID) {
            volatile float* vp = g_part;
            fred[tid] = vp[tid];
        }
        __syncthreads();
        #pragma unroll
        for (int off = GRID / 2; off > 0; off >>= 1) {
            if (tid < off) fred[tid] += fred[tid + off];
            __syncthreads();
        }
        if (tid == 0) out[0] = fred[0];
    }
}

// ---------------------------------------------------------------------------
extern "C" void kernel_launch(void* const* d_in, const int* in_sizes, int n_in,
                              void* d_out, int out_size)
{
    const float* x             = (const float*)d_in[0];
    const float* weight_logits = (const float*)d_in[1];
    const float* means         = (const float*)d_in[2];
    const float* log_vars      = (const float*)d_in[3];
    float* out = (float*)d_out;

    gmm_fused<<<GRID, TPB>>>(x, weight_logits, means, log_vars, out);
}

// round 16
// speedup vs baseline: 1.3719x; 1.3719x over previous
#include <cuda_runtime.h>
#include <cuda_bf16.h>
#include <math.h>

// Problem constants
#define NN 8192
#define KK 64
#define NB 1024
#define XLO (-6.0f)
#define BW_INVF (1024.0f / 12.0f)   // 1/bucket_width = 85.3333
#define RWIN 9                      // window +/-9 buckets; excluded |d| > 0.1055 -> exp contributes < 1e-38
#define WBINS (2 * RWIN + 1)
#define GRID 256
#define TPB 512
#define NGRP 4                      // own buckets per block (stride 256 in bucket space)
#define WCAP 1024                   // per-group window capacity (peak ~730)
#define OCAP 64                     // per-group own capacity (peak ~40)
#define PSPLIT 16                   // threads per own element in KDE

// -8192 * log2(e); +21 bias makes ex2 output pre-scaled by 2^21 for int quantization
#define C2L (-11818.558f)
#define QBIAS 21.0f
// invZ / 2^21  (invZ = 1/(bw*sqrt(2pi)*N))
#define INVZQ ((float)(1.0 / (0.0078125 * 2.5066282746310002 * 8192.0 * 2097152.0)))

// Persistent global state (monotonic counter survives graph replays)
__device__ int   g_cnt;
__device__ float g_part[GRID];

__device__ __forceinline__ float ex2f(float y) {
    float r;
    asm("ex2.approx.f32 %0, %1;" : "=f"(r) : "f"(y));
    return r;
}

__global__ void __launch_bounds__(TPB, 3)
gmm_fused(const float* __restrict__ x,
          const float* __restrict__ weight_logits,
          const float* __restrict__ means,
          const float* __restrict__ log_vars,
          float* __restrict__ out)
{
    __shared__ float win[NGRP][WCAP];   // window values (atomic order — OK, int accumulation)
    __shared__ float own[NGRP][OCAP];   // own-bucket values (atomic order — OK)
    __shared__ int   wcnt[NGRP], ocnt[NGRP];
    __shared__ float sa[KK], sc[KK], smu[KK];
    __shared__ float red[TPB / 32];
    __shared__ float fred[GRID];
    __shared__ int   slast;

    const int tid  = threadIdx.x;
    const int blk  = blockIdx.x;
    const int lane = tid & 31;
    const int w    = tid >> 5;
    const unsigned FULL = 0xffffffffu;

    if (tid < NGRP) { wcnt[tid] = 0; ocnt[tid] = 0; }

    // ---- GMM constants (warp 1, redundant per block) --------------------
    if (w == 1) {
        const float TWO_PI = 6.283185307179586f;
        float l0 = weight_logits[lane], l1 = weight_logits[lane + 32];
        float m = fmaxf(l0, l1);
        #pragma unroll
        for (int o = 16; o > 0; o >>= 1) m = fmaxf(m, __shfl_xor_sync(FULL, m, o));
        float e0 = expf(l0 - m), e1 = expf(l1 - m);
        float s = e0 + e1;
        #pragma unroll
        for (int o = 16; o > 0; o >>= 1) s += __shfl_xor_sync(FULL, s, o);
        float invs = 1.0f / s;

        float var0 = expf(log_vars[lane]);
        sa[lane]  = e0 * invs * rsqrtf(TWO_PI * var0);
        sc[lane]  = -0.5f / var0;
        smu[lane] = means[lane];
        float var1 = expf(log_vars[lane + 32]);
        sa[lane + 32]  = e1 * invs * rsqrtf(TWO_PI * var1);
        sc[lane + 32]  = -0.5f / var1;
        smu[lane + 32] = means[lane + 32];
    }
    __syncthreads();

    // ---- P1: classify all x into this block's 4 window/own groups -------
    // bucket b; q = b + 265 - blk; r = q&255 in [0,19), g = (q>>8)-1 in [0,4)
    {
        const float4* x4 = (const float4*)x;
        const int qoff = 256 + RWIN - blk;
        #pragma unroll
        for (int t = 0; t < NN / (TPB * 4); ++t) {
            float4 q4 = x4[t * TPB + tid];
            #pragma unroll
            for (int c = 0; c < 4; ++c) {
                float v = (c == 0) ? q4.x : (c == 1) ? q4.y : (c == 2) ? q4.z : q4.w;
                int b = __float2int_rd(fmaf(v, BW_INVF, 512.0f));  // (v-XLO)*BW_INVF
                b = min(max(b, 0), NB - 1);
                int q = b + qoff;
                int r = q & 255;
                int g = (q >> 8) - 1;
                if (r < WBINS && (unsigned)g < NGRP) {
                    int p = atomicAdd(&wcnt[g], 1);
                    if (p < WCAP) win[g][p] = v;
                    if (r == RWIN) {
                        int o = atomicAdd(&ocnt[g], 1);
                        if (o < OCAP) own[g][o] = v;
                    }
                }
            }
        }
    }
    __syncthreads();

    // ---- P2: KDE (int-quantized, order-independent) + mixture -----------
    const int oc0 = min(ocnt[0], OCAP), oc1 = min(ocnt[1], OCAP);
    const int oc2 = min(ocnt[2], OCAP), oc3 = min(ocnt[3], OCAP);
    const int oo1 = oc0, oo2 = oc0 + oc1, oo3 = oc0 + oc1 + oc2;
    const int M   = oo3 + oc3;
    const int ESL = TPB / PSPLIT;                // 32 element-slots per pass
    const int Mup = (M + ESL - 1) / ESL * ESL;
    const int e0  = tid >> 4;
    const int p   = tid & (PSPLIT - 1);

    float acc = 0.0f;
    for (int e = e0; e < Mup; e += ESL) {
        const bool active = (e < M);
        int g = 0, og = 0;
        if (active) {
            g  = (e >= oo1) + (e >= oo2) + (e >= oo3);
            og = (g == 0) ? 0 : (g == 1) ? oo1 : (g == 2) ? oo2 : oo3;
        }
        float xi = 0.0f;
        int a = 0, bnd = 0;
        const float* wg = win[g];
        if (active) {
            xi  = own[g][e - og];
            int cnt = min(wcnt[g], WCAP);
            a   = (p * cnt) >> 4;
            bnd = ((p + 1) * cnt) >> 4;
        }

        // int-quantized KDE over this part's contiguous range (4 indep accums)
        int s0 = 0, s1 = 0, s2 = 0, s3 = 0;
        int k = a;
        for (; k + 4 <= bnd; k += 4) {
            float d0 = xi - wg[k + 0], d1 = xi - wg[k + 1];
            float d2 = xi - wg[k + 2], d3 = xi - wg[k + 3];
            s0 += __float2int_rn(ex2f(fmaf(d0 * d0, C2L, QBIAS)));
            s1 += __float2int_rn(ex2f(fmaf(d1 * d1, C2L, QBIAS)));
            s2 += __float2int_rn(ex2f(fmaf(d2 * d2, C2L, QBIAS)));
            s3 += __float2int_rn(ex2f(fmaf(d3 * d3, C2L, QBIAS)));
        }
        for (; k < bnd; ++k) {
            float d = xi - wg[k];
            s0 += __float2int_rn(ex2f(fmaf(d * d, C2L, QBIAS)));
        }
        int ks = (s0 + s1) + (s2 + s3);

        // this part's 4 mixture components (fixed order -> deterministic)
        float m = 0.0f;
        #pragma unroll
        for (int c = p * 4; c < p * 4 + 4; ++c) {
            float d = xi - smu[c];
            m += sa[c] * __expf(sc[c] * d * d);
        }

        // combine 16 parts: int kde (exact, order-free) + float mix (fixed tree)
        #pragma unroll
        for (int o = 8; o > 0; o >>= 1) {
            ks += __shfl_xor_sync(FULL, ks, o, 16);
            m  += __shfl_xor_sync(FULL, m,  o, 16);
        }
        if (p == 0 && active) {
            float diff = m - (float)ks * INVZQ;
            acc += diff * diff;
        }
    }

    // ---- block reduction (fixed order) -----------------------------------
    #pragma unroll
    for (int o = 16; o > 0; o >>= 1) acc += __shfl_xor_sync(FULL, acc, o);
    if (lane == 0) red[w] = acc;
    __syncthreads();
    if (w == 0) {
        float bsum = (lane < TPB / 32) ? red[lane] : 0.0f;
        #pragma unroll
        for (int o = 16; o > 0; o >>= 1) bsum += __shfl_xor_sync(FULL, bsum, o);
        if (lane == 0) {
            g_part[blk] = bsum;
            __threadfence();
            int old = atomicAdd(&g_cnt, 1);
            slast = (((old + 1) & (GRID - 1)) == 0);
        }
    }
    __syncthreads();

    // ---- last block: fixed-order final sum --------------------------------
    if (slast) {
        if (tid < GRID) {
            volatile float* vp = g_part;
            fred[tid] = vp[tid];
        }
        __syncthreads();
        #pragma unroll
        for (int off = GRID / 2; off > 0; off >>= 1) {
            if (tid < off) fred[tid] += fred[tid + off];
            __syncthreads();
        }
        if (tid == 0) out[0] = fred[0];
    }
}

// ---------------------------------------------------------------------------
extern "C" void kernel_launch(void* const* d_in, const int* in_sizes, int n_in,
                              void* d_out, int out_size)
{
    const float* x             = (const float*)d_in[0];
    const float* weight_logits = (const float*)d_in[1];
    const float* means         = (const float*)d_in[2];
    const float* log_vars      = (const float*)d_in[3];
    float* out = (float*)d_out;

    gmm_fused<<<GRID, TPB>>>(x, weight_logits, means, log_vars, out);
}